// round 16
// baseline (speedup 1.0000x reference)
#include <cuda_runtime.h>
#include <math.h>
#include <stdint.h>

// Problem constants
#define BN   32
#define CC   3072
#define KK   11
#define HW   784
#define NCLS 200
#define NCH  12           // c-chunks for k_ab
#define CCH  (CC / NCH)   // 256 channels per chunk

typedef unsigned long long ull;

// Scratch (device globals; no allocation allowed)
__device__ float g_ab_part[NCH * BN * KK * HW];   // 13.2 MB partial ab
__device__ float g_asq[KK];
__device__ float g_g[BN * CC];                    // sum_k feat_mod

// ---------------------------------------------------------------------------
// f32x2 + cp.async helpers
// ---------------------------------------------------------------------------
__device__ __forceinline__ void ffma2(ull& d, ull a, ull b) {
    asm("fma.rn.f32x2 %0, %1, %2, %0;" : "+l"(d) : "l"(a), "l"(b));
}
__device__ __forceinline__ ull pack2(float lo, float hi) {
    ull r; asm("mov.b64 %0, {%1, %2};" : "=l"(r) : "f"(lo), "f"(hi)); return r;
}
__device__ __forceinline__ float2 unpack2(ull v) {
    float2 r; asm("mov.b64 {%0, %1}, %2;" : "=f"(r.x), "=f"(r.y) : "l"(v)); return r;
}
__device__ __forceinline__ void cp16(uint32_t smem_dst, const void* gsrc) {
    asm volatile("cp.async.cg.shared.global [%0], [%1], 16;"
                 :: "r"(smem_dst), "l"(gsrc));
}
__device__ __forceinline__ void cp_commit() {
    asm volatile("cp.async.commit_group;");
}
template <int N>
__device__ __forceinline__ void cp_wait() {
    asm volatile("cp.async.wait_group %0;" :: "n"(N));
}
__device__ __forceinline__ uint32_t sptr(const void* p) {
    return (uint32_t)__cvta_generic_to_shared(p);
}

// ---------------------------------------------------------------------------
// Kernel 0: a_sq[k] = sum_c w_land[k,c]^2
// ---------------------------------------------------------------------------
__global__ void k_asq(const float* __restrict__ wl) {
    int k = blockIdx.x;
    int tid = threadIdx.x;
    float s = 0.f;
    for (int c = tid; c < CC; c += 128) {
        float w = wl[k * CC + c];
        s += w * w;
    }
    __shared__ float red[128];
    red[tid] = s;
    __syncthreads();
    for (int o = 64; o; o >>= 1) {
        if (tid < o) red[tid] += red[tid + o];
        __syncthreads();
    }
    if (tid == 0) g_asq[k] = red[0];
}

// ---------------------------------------------------------------------------
// Kernel 1: SELF-SERVICE partial ab (unchanged from R15 — coalesced copies,
// no per-stage barriers). grid (NCH=12, BN), block 196.
// ---------------------------------------------------------------------------
#define AB_SCH    4
#define AB_STAGES (CCH / AB_SCH)   // 64
__global__ void __launch_bounds__(196, 3) k_ab(const float* __restrict__ x,
                                               const float* __restrict__ wl) {
    extern __shared__ char smem_ab[];
    ull* ws2 = (ull*)smem_ab;                       // [KK*CCH] {w,w} 22528 B
    char* xr = smem_ab + 22528;                     // ring: 4 x 12544 B

    const int ch = blockIdx.x;
    const int b  = blockIdx.y;
    const int c0 = ch * CCH;
    const int tid = threadIdx.x;

    const float4* x4 = (const float4*)x;
    const float4* xbase = x4 + ((size_t)b * CC + c0) * 196 + tid;

#define AB_KICK(s) {                                                          \
        uint32_t d_ = sptr(xr + ((s) & 3) * 12544) + tid * 16;                \
        const float4* src_ = xbase + (size_t)((s) * AB_SCH) * 196;            \
        cp16(d_ + 0 * 3136, src_ + 0 * 196);                                  \
        cp16(d_ + 1 * 3136, src_ + 1 * 196);                                  \
        cp16(d_ + 2 * 3136, src_ + 2 * 196);                                  \
        cp16(d_ + 3 * 3136, src_ + 3 * 196);                                  \
        cp_commit();                                                          \
    }

    AB_KICK(0); AB_KICK(1); AB_KICK(2);

    for (int i = tid; i < KK * CCH; i += 196) {
        int k = i >> 8, c = i & (CCH - 1);
        float w = wl[k * CC + c0 + c];
        ws2[i] = pack2(w, w);
    }
    __syncthreads();    // only for ws2 visibility (once)

    ull acc[KK][2];
#pragma unroll
    for (int k = 0; k < KK; ++k) { acc[k][0] = 0ull; acc[k][1] = 0ull; }

    const ulonglong2* ws22 = (const ulonglong2*)ws2;   // [KK][CCH/2]

#pragma unroll 1
    for (int s = 0; s < AB_STAGES; ++s) {
        if (s <= AB_STAGES - 3)      cp_wait<2>();
        else if (s == AB_STAGES - 2) cp_wait<1>();
        else                         cp_wait<0>();

        const ulonglong2* xq = (const ulonglong2*)(xr + (s & 3) * 12544);
        ulonglong2 x0 = xq[0 * 196 + tid];
        ulonglong2 x1 = xq[1 * 196 + tid];
        ulonglong2 x2 = xq[2 * 196 + tid];
        ulonglong2 x3 = xq[3 * 196 + tid];
#pragma unroll
        for (int k = 0; k < KK; ++k) {
            ulonglong2 w01 = ws22[k * (CCH / 2) + 2 * s];
            ulonglong2 w23 = ws22[k * (CCH / 2) + 2 * s + 1];
            ffma2(acc[k][0], x0.x, w01.x); ffma2(acc[k][1], x0.y, w01.x);
            ffma2(acc[k][0], x1.x, w01.y); ffma2(acc[k][1], x1.y, w01.y);
            ffma2(acc[k][0], x2.x, w23.x); ffma2(acc[k][1], x2.y, w23.x);
            ffma2(acc[k][0], x3.x, w23.y); ffma2(acc[k][1], x3.y, w23.y);
        }

        if (s + 3 < AB_STAGES) AB_KICK(s + 3);
    }

    ulonglong2* gp2 = reinterpret_cast<ulonglong2*>(g_ab_part);
    size_t base2 = (size_t)(ch * BN + b) * KK * 196;
#pragma unroll
    for (int k = 0; k < KK; ++k) {
        ulonglong2 v; v.x = acc[k][0]; v.y = acc[k][1];
        gp2[base2 + (size_t)k * 196 + tid] = v;
    }
#undef AB_KICK
}

// ---------------------------------------------------------------------------
// Kernel 2: combine chunks, softmax over K (b_sq cancels), write maps.
// grid (BN, 4 pixel slices), block 196 (1 pixel per thread)
// ---------------------------------------------------------------------------
__global__ void k_softmax(float* __restrict__ maps) {
    const int b = blockIdx.x;
    const int p = blockIdx.y * 196 + threadIdx.x;

    __shared__ float asq[KK];
    if (threadIdx.x < KK) asq[threadIdx.x] = g_asq[threadIdx.x];
    __syncthreads();

    float s[KK];
#pragma unroll
    for (int k = 0; k < KK; ++k) s[k] = 0.f;

#pragma unroll
    for (int ch = 0; ch < NCH; ++ch) {
        size_t base = ((size_t)(ch * BN + b) * KK) * HW + p;
#pragma unroll
        for (int k = 0; k < KK; ++k)
            s[k] += g_ab_part[base + (size_t)k * HW];
    }
    float mx = -1e30f;
#pragma unroll
    for (int k = 0; k < KK; ++k) {
        s[k] = 2.f * s[k] - asq[k];
        mx = fmaxf(mx, s[k]);
    }
    float sum = 0.f;
#pragma unroll
    for (int k = 0; k < KK; ++k) {
        s[k] = __expf(s[k] - mx);
        sum += s[k];
    }
    float inv = 1.f / sum;
#pragma unroll
    for (int k = 0; k < KK; ++k)
        maps[((size_t)(b * KK + k)) * HW + p] = s[k] * inv;
}

// ---------------------------------------------------------------------------
// Kernel 3: COALESCED-LDG feat. grid (CC/16 = 192, BN), block 256.
// Warp owns 2 channels; lanes span pixels -> every x load is a fully
// coalesced LDG.128; pairs of iterations front-batched -> 4 LDGs in flight.
// maps in smem, banked conflict-free LDS.128. acc = 2*11 ull = 44 regs.
// No cp.async, no rings, no per-stage barriers. 3 blocks/SM (24 warps).
// Smem: maps only, 34496 B.
// ---------------------------------------------------------------------------
__global__ void __launch_bounds__(256, 3) k_feat(const float* __restrict__ x,
                                                 const float* __restrict__ maps,
                                                 const float* __restrict__ mod,
                                                 float* __restrict__ feat) {
    extern __shared__ char smem_ft[];
    ull* maps_s = (ull*)smem_ft;                    // [KK*392] 34496 B

    const int b    = (BN - 1) - blockIdx.y;         // reversed for L2 overlap
    const int tid  = threadIdx.x;
    const int warp = tid >> 5, lane = tid & 31;
    const int c0   = blockIdx.x * 16 + warp * 2;    // 2 channels per warp

    // load maps once (coalesced, mostly L2-hot)
    const ull* mg = reinterpret_cast<const ull*>(maps + (size_t)b * KK * HW);
    for (int i = tid; i < KK * 392; i += 256) maps_s[i] = mg[i];
    __syncthreads();

    const ulonglong2* m2  = (const ulonglong2*)maps_s;                   // [KK][196]
    const ulonglong2* xr0 = (const ulonglong2*)(x + ((size_t)b * CC + c0) * HW);
    const ulonglong2* xr1 = (const ulonglong2*)(x + ((size_t)b * CC + c0 + 1) * HW);

    ull acc0[KK], acc1[KK];
#pragma unroll
    for (int k = 0; k < KK; ++k) { acc0[k] = 0ull; acc1[k] = 0ull; }

    // 196 ulonglong2 per row; q = lane + 32*i, i = 0..5 full, i = 6 partial.
#pragma unroll
    for (int i = 0; i < 6; i += 2) {
        const int qa = lane + 32 * i;
        const int qb = qa + 32;
        // 4 independent coalesced LDG.128 front-batched
        ulonglong2 a0 = xr0[qa];
        ulonglong2 a1 = xr1[qa];
        ulonglong2 b0 = xr0[qb];
        ulonglong2 b1 = xr1[qb];
#pragma unroll
        for (int k = 0; k < KK; ++k) {
            ulonglong2 ma = m2[k * 196 + qa];       // conflict-free LDS.128
            ffma2(acc0[k], a0.x, ma.x); ffma2(acc0[k], a0.y, ma.y);
            ffma2(acc1[k], a1.x, ma.x); ffma2(acc1[k], a1.y, ma.y);
        }
#pragma unroll
        for (int k = 0; k < KK; ++k) {
            ulonglong2 mb = m2[k * 196 + qb];
            ffma2(acc0[k], b0.x, mb.x); ffma2(acc0[k], b0.y, mb.y);
            ffma2(acc1[k], b1.x, mb.x); ffma2(acc1[k], b1.y, mb.y);
        }
    }
    // tail: q = lane + 192, valid for lane < 4
    if (lane < 4) {
        const int q = lane + 192;
        ulonglong2 a0 = xr0[q];
        ulonglong2 a1 = xr1[q];
#pragma unroll
        for (int k = 0; k < KK; ++k) {
            ulonglong2 m = m2[k * 196 + q];
            ffma2(acc0[k], a0.x, m.x); ffma2(acc0[k], a0.y, m.y);
            ffma2(acc1[k], a1.x, m.x); ffma2(acc1[k], a1.y, m.y);
        }
    }

    // warp reduce + epilogue (lane 0 writes 2 channels)
    const float inv_hw = 1.f / (float)HW;
    float gs0 = 0.f, gs1 = 0.f;
#pragma unroll
    for (int k = 0; k < KK; ++k) {
        float2 v0 = unpack2(acc0[k]);
        float2 v1 = unpack2(acc1[k]);
        float s0 = v0.x + v0.y;
        float s1 = v1.x + v1.y;
#pragma unroll
        for (int o = 16; o; o >>= 1) {
            s0 += __shfl_down_sync(0xffffffffu, s0, o);
            s1 += __shfl_down_sync(0xffffffffu, s1, o);
        }
        if (lane == 0) {
            float r0 = s0 * inv_hw * mod[(c0 + 0) * KK + k];
            float r1 = s1 * inv_hw * mod[(c0 + 1) * KK + k];
            feat[((size_t)b * CC + c0 + 0) * KK + k] = r0;
            feat[((size_t)b * CC + c0 + 1) * KK + k] = r1;
            gs0 += r0;
            gs1 += r1;
        }
    }
    if (lane == 0) {
        g_g[b * CC + c0 + 0] = gs0;
        g_g[b * CC + c0 + 1] = gs1;
    }
}

// ---------------------------------------------------------------------------
// Kernel 4: attn[b,k] = sum_p maps[b,k,p].  grid (BN, KK), block 256
// ---------------------------------------------------------------------------
__global__ void k_attn(const float* __restrict__ maps, float* __restrict__ attn) {
    const int b = blockIdx.x, k = blockIdx.y, tid = threadIdx.x;
    float s = 0.f;
    const float* mp = maps + ((size_t)b * KK + k) * HW;
    for (int i = tid; i < HW; i += 256) s += mp[i];
    __shared__ float red[256];
    red[tid] = s;
    __syncthreads();
    for (int o = 128; o; o >>= 1) {
        if (tid < o) red[tid] += red[tid + o];
        __syncthreads();
    }
    if (tid == 0) attn[b * KK + k] = red[0];
}

// ---------------------------------------------------------------------------
// Kernel 5: scores[b,n] = sum_c g[b,c] * w_cls[n,c]; 4 batches per block.
// grid (NCLS, BN/4), block 128
// ---------------------------------------------------------------------------
__global__ void k_scores(const float* __restrict__ wcls,
                         float* __restrict__ scores) {
    const int n = blockIdx.x;
    const int b0 = blockIdx.y * 4;
    const int tid = threadIdx.x;
    float s0 = 0.f, s1 = 0.f, s2 = 0.f, s3 = 0.f;
    const float* wn = wcls + (size_t)n * CC;
    for (int c = tid; c < CC; c += 128) {
        float w = wn[c];
        s0 = fmaf(w, g_g[(b0 + 0) * CC + c], s0);
        s1 = fmaf(w, g_g[(b0 + 1) * CC + c], s1);
        s2 = fmaf(w, g_g[(b0 + 2) * CC + c], s2);
        s3 = fmaf(w, g_g[(b0 + 3) * CC + c], s3);
    }
    __shared__ float red[4][128];
    red[0][tid] = s0; red[1][tid] = s1; red[2][tid] = s2; red[3][tid] = s3;
    __syncthreads();
    for (int o = 64; o; o >>= 1) {
        if (tid < o) {
            red[0][tid] += red[0][tid + o];
            red[1][tid] += red[1][tid + o];
            red[2][tid] += red[2][tid + o];
            red[3][tid] += red[3][tid + o];
        }
        __syncthreads();
    }
    if (tid == 0) {
#pragma unroll
        for (int j = 0; j < 4; ++j)
            scores[(b0 + j) * NCLS + n] = red[j][0];
    }
}

// ---------------------------------------------------------------------------
extern "C" void kernel_launch(void* const* d_in, const int* in_sizes, int n_in,
                              void* d_out, int out_size) {
    const float* x    = (const float*)d_in[0];
    const float* wl   = (const float*)d_in[1];
    const float* mod  = (const float*)d_in[2];
    const float* wcls = (const float*)d_in[3];

    float* out    = (float*)d_out;
    float* feat   = out;                                   // (B,C,K)
    float* scores = out + (size_t)BN * CC * KK;            // (B,NC)
    float* maps   = scores + (size_t)BN * NCLS;            // (B,K,HW)
    float* attn   = maps + (size_t)BN * KK * HW;           // (B,K)

    cudaFuncSetAttribute(k_ab,   cudaFuncAttributeMaxDynamicSharedMemorySize, 72704);
    cudaFuncSetAttribute(k_feat, cudaFuncAttributeMaxDynamicSharedMemorySize, 34496);

    k_asq<<<KK, 128>>>(wl);
    k_ab<<<dim3(NCH, BN), 196, 72704>>>(x, wl);
    k_softmax<<<dim3(BN, 4), 196>>>(maps);
    k_feat<<<dim3(CC / 16, BN), 256, 34496>>>(x, maps, mod, feat);
    k_attn<<<dim3(BN, KK), 256>>>(maps, attn);
    k_scores<<<dim3(NCLS, BN / 4), 128>>>(wcls, scores);
}